// round 6
// baseline (speedup 1.0000x reference)
#include <cuda_runtime.h>
#include <cuda_bf16.h>
#include <cstdint>

typedef unsigned long long u64;

#define B_DIM 4096
#define T_DIM 1024
#define VOCAB 32000
#define HID 16

// ---------------- scratch (no allocations allowed) ----------------
__device__ float g_P[VOCAB * HID];   // projected embedding table: Wx@e + b (2 MB)
__device__ float g_H[B_DIM * HID];   // final hidden states (256 KB)

// ---------------- f32x2 helpers ----------------
__device__ __forceinline__ u64 pack2(float x, float y) {
    u64 r; asm("mov.b64 %0, {%1, %2};" : "=l"(r) : "f"(x), "f"(y)); return r;
}
__device__ __forceinline__ float2 unpack2(u64 v) {
    float2 f; asm("mov.b64 {%0, %1}, %2;" : "=f"(f.x), "=f"(f.y) : "l"(v)); return f;
}
__device__ __forceinline__ u64 ffma2(u64 a, u64 b, u64 c) {
    u64 d; asm("fma.rn.f32x2 %0, %1, %2, %3;" : "=l"(d) : "l"(a), "l"(b), "l"(c)); return d;
}

// ---------------- kernel 0: P = embed @ Wx^T + b ----------------
__global__ __launch_bounds__(256) void prep_kernel(
    const float* __restrict__ embed, const float* __restrict__ Wx_w,
    const float* __restrict__ Wx_b)
{
    __shared__ float e[16][16];
    int t = threadIdx.x;
    int v0 = blockIdx.x * 16;

    if (t < 64) {
        int vv = t >> 2, c = t & 3;
        ((float4*)e[vv])[c] = __ldg((const float4*)(embed + (size_t)(v0 + vv) * 16) + c);
    }
    __syncthreads();

    int vl = t >> 4, i = t & 15;
    const float4* er = (const float4*)e[vl];
    float4 e0 = er[0], e1 = er[1], e2 = er[2], e3 = er[3];
    const float* wr = Wx_w + i * 16;

    float a0 = __ldg(Wx_b + i), a1 = 0.f, a2 = 0.f, a3 = 0.f;
    a0 = fmaf(__ldg(wr + 0),  e0.x, a0);  a1 = fmaf(__ldg(wr + 1),  e0.y, a1);
    a2 = fmaf(__ldg(wr + 2),  e0.z, a2);  a3 = fmaf(__ldg(wr + 3),  e0.w, a3);
    a0 = fmaf(__ldg(wr + 4),  e1.x, a0);  a1 = fmaf(__ldg(wr + 5),  e1.y, a1);
    a2 = fmaf(__ldg(wr + 6),  e1.z, a2);  a3 = fmaf(__ldg(wr + 7),  e1.w, a3);
    a0 = fmaf(__ldg(wr + 8),  e2.x, a0);  a1 = fmaf(__ldg(wr + 9),  e2.y, a1);
    a2 = fmaf(__ldg(wr + 10), e2.z, a2);  a3 = fmaf(__ldg(wr + 11), e2.w, a3);
    a0 = fmaf(__ldg(wr + 12), e3.x, a0);  a1 = fmaf(__ldg(wr + 13), e3.y, a1);
    a2 = fmaf(__ldg(wr + 14), e3.z, a2);  a3 = fmaf(__ldg(wr + 15), e3.w, a3);

    g_P[(size_t)(v0 + vl) * 16 + i] = (a0 + a1) + (a2 + a3);
}

// ---------------- kernel 1: sequential recurrence, 8-step pipelined ----------------
// Lane (row, i) keeps h[i]; exchange via double-buffered smem broadcast
// (1 STS.32 + 1 __syncwarp per step, 4 LDS.128 broadcast reads).
// Each thread drives rows rA and rB = rA+2 (independent chains interleave).
// P-gathers for block k+1 issued at the START of block k (slack ~8 steps);
// seq tokens prefetched two blocks ahead. This keeps L2 latency (~240 cyc
// seq + ~240 cyc gather, serially dependent) out of the recurrence chain.

__device__ __forceinline__ float tanh_fast(float z) {
    float e = __expf(2.0f * z);
    return 1.0f - __fdividef(2.0f, e + 1.0f);
}

__device__ __forceinline__ float stepdot(const float* __restrict__ w,
                                         const float4* __restrict__ hrow, float xp) {
    float4 h0 = hrow[0], h1 = hrow[1], h2 = hrow[2], h3 = hrow[3];
    float a0 = xp, a1 = 0.f, a2 = 0.f, a3 = 0.f;
    a0 = fmaf(w[0],  h0.x, a0);  a1 = fmaf(w[1],  h0.y, a1);
    a2 = fmaf(w[2],  h0.z, a2);  a3 = fmaf(w[3],  h0.w, a3);
    a0 = fmaf(w[4],  h1.x, a0);  a1 = fmaf(w[5],  h1.y, a1);
    a2 = fmaf(w[6],  h1.z, a2);  a3 = fmaf(w[7],  h1.w, a3);
    a0 = fmaf(w[8],  h2.x, a0);  a1 = fmaf(w[9],  h2.y, a1);
    a2 = fmaf(w[10], h2.z, a2);  a3 = fmaf(w[11], h2.w, a3);
    a0 = fmaf(w[12], h3.x, a0);  a1 = fmaf(w[13], h3.y, a1);
    a2 = fmaf(w[14], h3.z, a2);  a3 = fmaf(w[15], h3.w, a3);
    return tanh_fast((a0 + a1) + (a2 + a3));
}

__global__ __launch_bounds__(256) void rnn_kernel(
    const int* __restrict__ seq, const float* __restrict__ Wh)
{
    __shared__ float hbuf[2][32][16];

    int t = threadIdx.x;
    int warp = t >> 5, lane = t & 31;
    int i = lane & 15, rs = lane >> 4;
    int rA = warp * 4 + rs;          // block-local rows
    int rB = rA + 2;
    int gA = blockIdx.x * 32 + rA;   // global rows
    int gB = blockIdx.x * 32 + rB;

    float w[16];
    #pragma unroll
    for (int j = 0; j < 16; j++) w[j] = __ldg(Wh + i * 16 + j);

    const int* sA = seq + (size_t)gA * T_DIM;
    const int* sB = seq + (size_t)gB * T_DIM;
    const float* P = g_P;

    hbuf[0][rA][i] = 0.0f;
    hbuf[0][rB][i] = 0.0f;
    __syncwarp();

    float xA[8], xB[8];          // current block's input projections
    int4 nA0, nA1, nB0, nB1;     // tokens for NEXT block

    // -------- prologue: block 0 xp + block 1 tokens --------
    {
        int4 a0 = __ldg((const int4*)(sA + 0));
        int4 a1 = __ldg((const int4*)(sA + 4));
        int4 b0 = __ldg((const int4*)(sB + 0));
        int4 b1 = __ldg((const int4*)(sB + 4));
        xA[0] = __ldg(P + (size_t)a0.x * 16 + i);
        xA[1] = __ldg(P + (size_t)a0.y * 16 + i);
        xA[2] = __ldg(P + (size_t)a0.z * 16 + i);
        xA[3] = __ldg(P + (size_t)a0.w * 16 + i);
        xA[4] = __ldg(P + (size_t)a1.x * 16 + i);
        xA[5] = __ldg(P + (size_t)a1.y * 16 + i);
        xA[6] = __ldg(P + (size_t)a1.z * 16 + i);
        xA[7] = __ldg(P + (size_t)a1.w * 16 + i);
        xB[0] = __ldg(P + (size_t)b0.x * 16 + i);
        xB[1] = __ldg(P + (size_t)b0.y * 16 + i);
        xB[2] = __ldg(P + (size_t)b0.z * 16 + i);
        xB[3] = __ldg(P + (size_t)b0.w * 16 + i);
        xB[4] = __ldg(P + (size_t)b1.x * 16 + i);
        xB[5] = __ldg(P + (size_t)b1.y * 16 + i);
        xB[6] = __ldg(P + (size_t)b1.z * 16 + i);
        xB[7] = __ldg(P + (size_t)b1.w * 16 + i);
        nA0 = __ldg((const int4*)(sA + 8));
        nA1 = __ldg((const int4*)(sA + 12));
        nB0 = __ldg((const int4*)(sB + 8));
        nB1 = __ldg((const int4*)(sB + 12));
    }

    #define RSTEP(SRC, DST, XA, XB)                                          \
        {                                                                    \
            float nAv = stepdot(w, (const float4*)hbuf[SRC][rA], XA);        \
            float nBv = stepdot(w, (const float4*)hbuf[SRC][rB], XB);        \
            hbuf[DST][rA][i] = nAv;                                          \
            hbuf[DST][rB][i] = nBv;                                          \
            __syncwarp();                                                    \
        }

    for (int tt = 0; tt < T_DIM; tt += 8) {
        // gather NEXT block's xp (tokens [tt+8, tt+16), prefetched last block)
        float pA[8], pB[8];
        pA[0] = __ldg(P + (size_t)nA0.x * 16 + i);
        pA[1] = __ldg(P + (size_t)nA0.y * 16 + i);
        pA[2] = __ldg(P + (size_t)nA0.z * 16 + i);
        pA[3] = __ldg(P + (size_t)nA0.w * 16 + i);
        pA[4] = __ldg(P + (size_t)nA1.x * 16 + i);
        pA[5] = __ldg(P + (size_t)nA1.y * 16 + i);
        pA[6] = __ldg(P + (size_t)nA1.z * 16 + i);
        pA[7] = __ldg(P + (size_t)nA1.w * 16 + i);
        pB[0] = __ldg(P + (size_t)nB0.x * 16 + i);
        pB[1] = __ldg(P + (size_t)nB0.y * 16 + i);
        pB[2] = __ldg(P + (size_t)nB0.z * 16 + i);
        pB[3] = __ldg(P + (size_t)nB0.w * 16 + i);
        pB[4] = __ldg(P + (size_t)nB1.x * 16 + i);
        pB[5] = __ldg(P + (size_t)nB1.y * 16 + i);
        pB[6] = __ldg(P + (size_t)nB1.z * 16 + i);
        pB[7] = __ldg(P + (size_t)nB1.w * 16 + i);

        // prefetch tokens two blocks ahead: [tt+16, tt+24) (clamped, unused tail)
        int tn = (tt + 16 < T_DIM) ? (tt + 16) : 0;
        nA0 = __ldg((const int4*)(sA + tn));
        nA1 = __ldg((const int4*)(sA + tn + 4));
        nB0 = __ldg((const int4*)(sB + tn));
        nB1 = __ldg((const int4*)(sB + tn + 4));

        // 8 recurrence steps on current xp (loads above drain underneath)
        RSTEP(0, 1, xA[0], xB[0])
        RSTEP(1, 0, xA[1], xB[1])
        RSTEP(0, 1, xA[2], xB[2])
        RSTEP(1, 0, xA[3], xB[3])
        RSTEP(0, 1, xA[4], xB[4])
        RSTEP(1, 0, xA[5], xB[5])
        RSTEP(0, 1, xA[6], xB[6])
        RSTEP(1, 0, xA[7], xB[7])

        #pragma unroll
        for (int k = 0; k < 8; k++) { xA[k] = pA[k]; xB[k] = pB[k]; }
    }
    #undef RSTEP

    // T_DIM % 8 == 0 -> final state is in buffer 0
    g_H[(size_t)gA * 16 + i] = hbuf[0][rA][i];
    g_H[(size_t)gB * 16 + i] = hbuf[0][rB][i];
}

// ---------------- kernel 2: out = H @ out_w^T + out_b via f32x2 ----------------
__global__ __launch_bounds__(256) void gemm_kernel(
    const float* __restrict__ out_w, const float* __restrict__ bias,
    float* __restrict__ out)
{
    __shared__ u64 hs[128 * 16];   // (h,h) packed, 16 KB

    int rb = blockIdx.y * 128;
    int vb = blockIdx.x * 1024;

    for (int idx = threadIdx.x; idx < 128 * 16; idx += 256) {
        float v = g_H[(size_t)rb * 16 + idx];
        hs[idx] = pack2(v, v);
    }
    __syncthreads();

    int v0 = vb + threadIdx.x * 4;
    if (v0 >= VOCAB) return;

    float wv[4][16];
    #pragma unroll
    for (int r = 0; r < 4; r++) {
        const float4* wr = (const float4*)(out_w + (size_t)(v0 + r) * 16);
        #pragma unroll
        for (int c = 0; c < 4; c++)
            ((float4*)wv[r])[c] = __ldg(wr + c);
    }
    u64 w2a[16], w2b[16];
    #pragma unroll
    for (int k = 0; k < 16; k++) {
        w2a[k] = pack2(wv[0][k], wv[1][k]);
        w2b[k] = pack2(wv[2][k], wv[3][k]);
    }
    u64 ba = *(const u64*)(bias + v0);
    u64 bb = *(const u64*)(bias + v0 + 2);

    for (int r = 0; r < 128; r++) {
        const ulonglong2* hp = (const ulonglong2*)(hs + r * 16);
        u64 aA = ba, aB = bb;
        #pragma unroll
        for (int k = 0; k < 16; k += 2) {
            ulonglong2 hh = hp[k >> 1];
            aA = ffma2(hh.x, w2a[k],     aA);
            aB = ffma2(hh.x, w2b[k],     aB);
            aA = ffma2(hh.y, w2a[k + 1], aA);
            aB = ffma2(hh.y, w2b[k + 1], aB);
        }
        float2 fa = unpack2(aA);
        float2 fb = unpack2(aB);
        *(float4*)(out + (size_t)(rb + r) * VOCAB + v0) =
            make_float4(fa.x, fa.y, fb.x, fb.y);
    }
}

// ---------------- launch ----------------
extern "C" void kernel_launch(void* const* d_in, const int* in_sizes, int n_in,
                              void* d_out, int out_size)
{
    const int*   seq   = (const int*)d_in[0];
    const float* embed = (const float*)d_in[1];
    const float* Wh    = (const float*)d_in[2];
    const float* Wx_w  = (const float*)d_in[3];
    const float* Wx_b  = (const float*)d_in[4];
    const float* out_w = (const float*)d_in[5];
    const float* out_b = (const float*)d_in[6];
    float* out = (float*)d_out;

    prep_kernel<<<VOCAB / 16, 256>>>(embed, Wx_w, Wx_b);          // 2000 blocks

    rnn_kernel<<<B_DIM / 32, 256>>>(seq, Wh);                     // 128 blocks

    dim3 ggrid((VOCAB + 1023) / 1024, B_DIM / 128);               // (32, 32)
    gemm_kernel<<<ggrid, 256>>>(out_w, out_b, out);
}

// round 8
// speedup vs baseline: 1.7091x; 1.7091x over previous
#include <cuda_runtime.h>
#include <cuda_bf16.h>
#include <cstdint>

typedef unsigned long long u64;

#define B_DIM 4096
#define T_DIM 1024
#define VOCAB 32000
#define HID 16

// ---------------- scratch (no allocations allowed) ----------------
__device__ float g_P[VOCAB * HID];   // projected embedding table: Wx@e + b (2 MB)
__device__ float g_H[B_DIM * HID];   // final hidden states (256 KB)

// ---------------- f32x2 helpers ----------------
__device__ __forceinline__ u64 pack2(float x, float y) {
    u64 r; asm("mov.b64 %0, {%1, %2};" : "=l"(r) : "f"(x), "f"(y)); return r;
}
__device__ __forceinline__ float2 unpack2(u64 v) {
    float2 f; asm("mov.b64 {%0, %1}, %2;" : "=f"(f.x), "=f"(f.y) : "l"(v)); return f;
}
__device__ __forceinline__ u64 ffma2(u64 a, u64 b, u64 c) {
    u64 d; asm("fma.rn.f32x2 %0, %1, %2, %3;" : "=l"(d) : "l"(a), "l"(b), "l"(c)); return d;
}

// ---------------- kernel 0: P = embed @ Wx^T + b ----------------
__global__ __launch_bounds__(256) void prep_kernel(
    const float* __restrict__ embed, const float* __restrict__ Wx_w,
    const float* __restrict__ Wx_b)
{
    __shared__ float e[16][16];
    int t = threadIdx.x;
    int v0 = blockIdx.x * 16;

    if (t < 64) {
        int vv = t >> 2, c = t & 3;
        ((float4*)e[vv])[c] = __ldg((const float4*)(embed + (size_t)(v0 + vv) * 16) + c);
    }
    __syncthreads();

    int vl = t >> 4, i = t & 15;
    const float4* er = (const float4*)e[vl];
    float4 e0 = er[0], e1 = er[1], e2 = er[2], e3 = er[3];
    const float* wr = Wx_w + i * 16;

    float a0 = __ldg(Wx_b + i), a1 = 0.f, a2 = 0.f, a3 = 0.f;
    a0 = fmaf(__ldg(wr + 0),  e0.x, a0);  a1 = fmaf(__ldg(wr + 1),  e0.y, a1);
    a2 = fmaf(__ldg(wr + 2),  e0.z, a2);  a3 = fmaf(__ldg(wr + 3),  e0.w, a3);
    a0 = fmaf(__ldg(wr + 4),  e1.x, a0);  a1 = fmaf(__ldg(wr + 5),  e1.y, a1);
    a2 = fmaf(__ldg(wr + 6),  e1.z, a2);  a3 = fmaf(__ldg(wr + 7),  e1.w, a3);
    a0 = fmaf(__ldg(wr + 8),  e2.x, a0);  a1 = fmaf(__ldg(wr + 9),  e2.y, a1);
    a2 = fmaf(__ldg(wr + 10), e2.z, a2);  a3 = fmaf(__ldg(wr + 11), e2.w, a3);
    a0 = fmaf(__ldg(wr + 12), e3.x, a0);  a1 = fmaf(__ldg(wr + 13), e3.y, a1);
    a2 = fmaf(__ldg(wr + 14), e3.z, a2);  a3 = fmaf(__ldg(wr + 15), e3.w, a3);

    g_P[(size_t)(v0 + vl) * 16 + i] = (a0 + a1) + (a2 + a3);
}

// ---------------- kernel 1: sequential recurrence ----------------
// ONE dependency chain per thread: lane (row, i) keeps h[i] of one row only.
// 16 lanes/row, 2 rows/warp, 16 rows/block, 256 blocks (all resident).
// Exchange: double-buffered smem broadcast (1 STS.32 + 1 __syncwarp per step,
// 4 two-way-broadcast LDS.128 reads). 4-step P-gather lookahead.

__device__ __forceinline__ float tanh_fast(float z) {
    float e = __expf(2.0f * z);
    return 1.0f - __fdividef(2.0f, e + 1.0f);
}

__device__ __forceinline__ float stepdot(const float* __restrict__ w,
                                         const float4* __restrict__ hrow, float xp) {
    float4 h0 = hrow[0], h1 = hrow[1], h2 = hrow[2], h3 = hrow[3];
    float a0 = xp, a1 = 0.f, a2 = 0.f, a3 = 0.f;
    a0 = fmaf(w[0],  h0.x, a0);  a1 = fmaf(w[1],  h0.y, a1);
    a2 = fmaf(w[2],  h0.z, a2);  a3 = fmaf(w[3],  h0.w, a3);
    a0 = fmaf(w[4],  h1.x, a0);  a1 = fmaf(w[5],  h1.y, a1);
    a2 = fmaf(w[6],  h1.z, a2);  a3 = fmaf(w[7],  h1.w, a3);
    a0 = fmaf(w[8],  h2.x, a0);  a1 = fmaf(w[9],  h2.y, a1);
    a2 = fmaf(w[10], h2.z, a2);  a3 = fmaf(w[11], h2.w, a3);
    a0 = fmaf(w[12], h3.x, a0);  a1 = fmaf(w[13], h3.y, a1);
    a2 = fmaf(w[14], h3.z, a2);  a3 = fmaf(w[15], h3.w, a3);
    return tanh_fast((a0 + a1) + (a2 + a3));
}

__global__ __launch_bounds__(256) void rnn_kernel(
    const int* __restrict__ seq, const float* __restrict__ Wh)
{
    __shared__ float hbuf[2][16][16];   // 16 rows per block

    int t = threadIdx.x;
    int lr = t >> 4;                  // block-local row 0..15 (2 rows per warp)
    int i  = t & 15;                  // hidden dim
    int g  = blockIdx.x * 16 + lr;    // global row  (grid = B_DIM/16 = 256)

    float w[16];
    #pragma unroll
    for (int j = 0; j < 16; j++) w[j] = __ldg(Wh + i * 16 + j);

    const int* sr = seq + (size_t)g * T_DIM;
    const float* P = g_P;

    hbuf[0][lr][i] = 0.0f;
    __syncwarp();

    // prologue: steps 0-3 xp + tokens for steps 4-7
    int4 tk = __ldg((const int4*)sr);
    float x0 = __ldg(P + (size_t)tk.x * 16 + i);
    float x1 = __ldg(P + (size_t)tk.y * 16 + i);
    float x2 = __ldg(P + (size_t)tk.z * 16 + i);
    float x3 = __ldg(P + (size_t)tk.w * 16 + i);
    int4 nt = __ldg((const int4*)(sr + 4));

    #define RSTEP(SRC, DST, X)                                               \
        {                                                                    \
            float nv = stepdot(w, (const float4*)hbuf[SRC][lr], X);          \
            hbuf[DST][lr][i] = nv;                                           \
            __syncwarp();                                                    \
        }

    for (int tt = 0; tt < T_DIM; tt += 4) {
        int tn = (tt + 8 < T_DIM) ? (tt + 8) : 0;       // clamped, tail unused
        int4 nn = __ldg((const int4*)(sr + tn));        // tokens two blocks out

        RSTEP(0, 1, x0)
        RSTEP(1, 0, x1)

        float p0 = __ldg(P + (size_t)nt.x * 16 + i);    // next block's xp
        float p1 = __ldg(P + (size_t)nt.y * 16 + i);
        float p2 = __ldg(P + (size_t)nt.z * 16 + i);
        float p3 = __ldg(P + (size_t)nt.w * 16 + i);

        RSTEP(0, 1, x2)
        RSTEP(1, 0, x3)

        x0 = p0; x1 = p1; x2 = p2; x3 = p3;
        nt = nn;
    }
    #undef RSTEP

    // T_DIM % 4 == 0 -> final state is in buffer 0; own lane wrote it
    g_H[(size_t)g * 16 + i] = hbuf[0][lr][i];
}

// ---------------- kernel 2: out = H @ out_w^T + out_b via f32x2 ----------------
__global__ __launch_bounds__(256) void gemm_kernel(
    const float* __restrict__ out_w, const float* __restrict__ bias,
    float* __restrict__ out)
{
    __shared__ u64 hs[128 * 16];   // (h,h) packed, 16 KB

    int rb = blockIdx.y * 128;
    int vb = blockIdx.x * 1024;

    for (int idx = threadIdx.x; idx < 128 * 16; idx += 256) {
        float v = g_H[(size_t)rb * 16 + idx];
        hs[idx] = pack2(v, v);
    }
    __syncthreads();

    int v0 = vb + threadIdx.x * 4;
    if (v0 >= VOCAB) return;

    float wv[4][16];
    #pragma unroll
    for (int r = 0; r < 4; r++) {
        const float4* wr = (const float4*)(out_w + (size_t)(v0 + r) * 16);
        #pragma unroll
        for (int c = 0; c < 4; c++)
            ((float4*)wv[r])[c] = __ldg(wr + c);
    }
    u64 w2a[16], w2b[16];
    #pragma unroll
    for (int k = 0; k < 16; k++) {
        w2a[k] = pack2(wv[0][k], wv[1][k]);
        w2b[k] = pack2(wv[2][k], wv[3][k]);
    }
    u64 ba = *(const u64*)(bias + v0);
    u64 bb = *(const u64*)(bias + v0 + 2);

    for (int r = 0; r < 128; r++) {
        const ulonglong2* hp = (const ulonglong2*)(hs + r * 16);
        u64 aA = ba, aB = bb;
        #pragma unroll
        for (int k = 0; k < 16; k += 2) {
            ulonglong2 hh = hp[k >> 1];
            aA = ffma2(hh.x, w2a[k],     aA);
            aB = ffma2(hh.x, w2b[k],     aB);
            aA = ffma2(hh.y, w2a[k + 1], aA);
            aB = ffma2(hh.y, w2b[k + 1], aB);
        }
        float2 fa = unpack2(aA);
        float2 fb = unpack2(aB);
        *(float4*)(out + (size_t)(rb + r) * VOCAB + v0) =
            make_float4(fa.x, fa.y, fb.x, fb.y);
    }
}

// ---------------- launch ----------------
extern "C" void kernel_launch(void* const* d_in, const int* in_sizes, int n_in,
                              void* d_out, int out_size)
{
    const int*   seq   = (const int*)d_in[0];
    const float* embed = (const float*)d_in[1];
    const float* Wh    = (const float*)d_in[2];
    const float* Wx_w  = (const float*)d_in[3];
    const float* Wx_b  = (const float*)d_in[4];
    const float* out_b = (const float*)d_in[6];
    const float* out_w = (const float*)d_in[5];
    float* out = (float*)d_out;

    prep_kernel<<<VOCAB / 16, 256>>>(embed, Wx_w, Wx_b);          // 2000 blocks

    rnn_kernel<<<B_DIM / 16, 256>>>(seq, Wh);                     // 256 blocks, 16 rows each

    dim3 ggrid((VOCAB + 1023) / 1024, B_DIM / 128);               // (32, 32)
    gemm_kernel<<<ggrid, 256>>>(out_w, out_b, out);
}

// round 9
// speedup vs baseline: 1.8090x; 1.0584x over previous
#include <cuda_runtime.h>
#include <cuda_bf16.h>
#include <cstdint>

typedef unsigned long long u64;

#define B_DIM 4096
#define T_DIM 1024
#define VOCAB 32000
#define HID 16

// ---------------- scratch (no allocations allowed) ----------------
__device__ float g_P[VOCAB * HID];   // projected embedding table: Wx@e + b (2 MB)
__device__ float g_H[B_DIM * HID];   // final hidden states (256 KB)

// ---------------- f32x2 helpers ----------------
__device__ __forceinline__ u64 pack2(float x, float y) {
    u64 r; asm("mov.b64 %0, {%1, %2};" : "=l"(r) : "f"(x), "f"(y)); return r;
}
__device__ __forceinline__ float2 unpack2(u64 v) {
    float2 f; asm("mov.b64 {%0, %1}, %2;" : "=f"(f.x), "=f"(f.y) : "l"(v)); return f;
}
__device__ __forceinline__ u64 ffma2(u64 a, u64 b, u64 c) {
    u64 d; asm("fma.rn.f32x2 %0, %1, %2, %3;" : "=l"(d) : "l"(a), "l"(b), "l"(c)); return d;
}

// ---------------- kernel 0: P = embed @ Wx^T + b ----------------
// 64 vocab rows per block (grid 500). Wx_w staged transposed in smem once.
__global__ __launch_bounds__(256) void prep_kernel(
    const float* __restrict__ embed, const float* __restrict__ Wx_w,
    const float* __restrict__ Wx_b)
{
    __shared__ float wsh[256];     // Wx_w transposed: wsh[j*16+i] = Wx_w[i*16+j]
    __shared__ float e[64][16];    // 64 embed rows

    int t = threadIdx.x;
    int v0 = blockIdx.x * 64;

    wsh[(t & 15) * 16 + (t >> 4)] = __ldg(Wx_w + t);
    {
        int vv = t >> 2, c = t & 3;
        ((float4*)e[vv])[c] = __ldg((const float4*)(embed + (size_t)(v0 + vv) * 16) + c);
    }
    __syncthreads();

    int i = t & 15;
    float w[16];
    #pragma unroll
    for (int j = 0; j < 16; j++) w[j] = wsh[j * 16 + i];   // conflict-free (consec i)
    float bias = __ldg(Wx_b + i);

    #pragma unroll
    for (int rep = 0; rep < 4; rep++) {
        int vl = (t >> 4) + rep * 16;
        const float4* er = (const float4*)e[vl];
        float4 e0 = er[0], e1 = er[1], e2 = er[2], e3 = er[3];
        float a0 = bias, a1 = 0.f, a2 = 0.f, a3 = 0.f;
        a0 = fmaf(w[0],  e0.x, a0);  a1 = fmaf(w[1],  e0.y, a1);
        a2 = fmaf(w[2],  e0.z, a2);  a3 = fmaf(w[3],  e0.w, a3);
        a0 = fmaf(w[4],  e1.x, a0);  a1 = fmaf(w[5],  e1.y, a1);
        a2 = fmaf(w[6],  e1.z, a2);  a3 = fmaf(w[7],  e1.w, a3);
        a0 = fmaf(w[8],  e2.x, a0);  a1 = fmaf(w[9],  e2.y, a1);
        a2 = fmaf(w[10], e2.z, a2);  a3 = fmaf(w[11], e2.w, a3);
        a0 = fmaf(w[12], e3.x, a0);  a1 = fmaf(w[13], e3.y, a1);
        a2 = fmaf(w[14], e3.z, a2);  a3 = fmaf(w[15], e3.w, a3);
        g_P[(size_t)(v0 + vl) * 16 + i] = (a0 + a1) + (a2 + a3);
    }
}

// ---------------- kernel 1: sequential recurrence ----------------
// One chain per thread; 16 lanes/row, 2 rows/warp, 16 rows/block, 256 blocks.
// Exchange: double-buffered smem broadcast; PER-ROW __syncwarp masks.
// seq tokens prefetched 3 blocks ahead (hides cold-DRAM ~600cyc);
// P gathers issued 1 block ahead of use with tokens already resident.

__device__ __forceinline__ float tanh_fast(float z) {
    // 1 - 2/(e^{2z}+1): mul, ex2, add, rcp, fma — minimal serial chain (~44 cyc)
    float r;
    asm("{\n\t"
        ".reg .f32 t;\n\t"
        "mul.f32 t, %1, 0f4038AA3B;\n\t"   // z * 2*log2(e)
        "ex2.approx.f32 t, t;\n\t"
        "add.f32 t, t, 0f3F800000;\n\t"    // + 1
        "rcp.approx.f32 t, t;\n\t"
        "fma.rn.f32 %0, t, 0fC0000000, 0f3F800000;\n\t"  // 1 - 2*t
        "}" : "=f"(r) : "f"(z));
    return r;
}

__device__ __forceinline__ float stepdot(const float* __restrict__ w,
                                         const float4* __restrict__ hrow, float xp) {
    float4 h0 = hrow[0], h1 = hrow[1], h2 = hrow[2], h3 = hrow[3];
    float a0 = xp, a1 = 0.f, a2 = 0.f, a3 = 0.f;
    a0 = fmaf(w[0],  h0.x, a0);  a1 = fmaf(w[1],  h0.y, a1);
    a2 = fmaf(w[2],  h0.z, a2);  a3 = fmaf(w[3],  h0.w, a3);
    a0 = fmaf(w[4],  h1.x, a0);  a1 = fmaf(w[5],  h1.y, a1);
    a2 = fmaf(w[6],  h1.z, a2);  a3 = fmaf(w[7],  h1.w, a3);
    a0 = fmaf(w[8],  h2.x, a0);  a1 = fmaf(w[9],  h2.y, a1);
    a2 = fmaf(w[10], h2.z, a2);  a3 = fmaf(w[11], h2.w, a3);
    a0 = fmaf(w[12], h3.x, a0);  a1 = fmaf(w[13], h3.y, a1);
    a2 = fmaf(w[14], h3.z, a2);  a3 = fmaf(w[15], h3.w, a3);
    return tanh_fast((a0 + a1) + (a2 + a3));
}

__global__ __launch_bounds__(256) void rnn_kernel(
    const int* __restrict__ seq, const float* __restrict__ Wh)
{
    __shared__ float hbuf[2][16][16];

    int t = threadIdx.x;
    int lr = t >> 4;                   // block-local row 0..15 (2 rows per warp)
    int i  = t & 15;
    int g  = blockIdx.x * 16 + lr;     // grid = B_DIM/16 = 256
    unsigned rowmask = 0xFFFFu << ((t >> 4 & 1) * 16);   // this row's 16 lanes

    float w[16];
    #pragma unroll
    for (int j = 0; j < 16; j++) w[j] = __ldg(Wh + i * 16 + j);

    const int* sr = seq + (size_t)g * T_DIM;
    const float* P = g_P;
    const float4* hb0 = (const float4*)hbuf[0][lr];
    const float4* hb1 = (const float4*)hbuf[1][lr];

    hbuf[0][lr][i] = 0.0f;
    __syncwarp(rowmask);

    // prologue: block0 xp; tokens for blocks 1 and 2 in flight
    int4 tk  = __ldg((const int4*)sr);
    float x0 = __ldg(P + (size_t)tk.x * 16 + i);
    float x1 = __ldg(P + (size_t)tk.y * 16 + i);
    float x2 = __ldg(P + (size_t)tk.z * 16 + i);
    float x3 = __ldg(P + (size_t)tk.w * 16 + i);
    int4 nt1 = __ldg((const int4*)(sr + 4));    // tokens block+1
    int4 nt2 = __ldg((const int4*)(sr + 8));    // tokens block+2

    #define RSTEP(SRCP, DSTIDX, X)                                           \
        {                                                                    \
            float nv = stepdot(w, SRCP, X);                                  \
            hbuf[DSTIDX][lr][i] = nv;                                        \
            __syncwarp(rowmask);                                             \
        }

    for (int tt = 0; tt < T_DIM; tt += 4) {
        int tn = (tt + 12 < T_DIM) ? (tt + 12) : 0;   // clamped, tail unused
        int4 nn = __ldg((const int4*)(sr + tn));      // tokens block+3

        RSTEP(hb0, 1, x0)
        RSTEP(hb1, 0, x1)

        float p0 = __ldg(P + (size_t)nt1.x * 16 + i); // next block's xp
        float p1 = __ldg(P + (size_t)nt1.y * 16 + i); // (tokens loaded 2 iters ago)
        float p2 = __ldg(P + (size_t)nt1.z * 16 + i);
        float p3 = __ldg(P + (size_t)nt1.w * 16 + i);

        RSTEP(hb0, 1, x2)
        RSTEP(hb1, 0, x3)

        x0 = p0; x1 = p1; x2 = p2; x3 = p3;
        nt1 = nt2; nt2 = nn;
    }
    #undef RSTEP

    // T_DIM % 4 == 0 -> final state in buffer 0
    g_H[(size_t)g * 16 + i] = hbuf[0][lr][i];
}

// ---------------- kernel 2: out = H @ out_w^T + out_b via f32x2 ----------------
// Streaming stores (__stcs): output is write-once, keep it out of L2.
__global__ __launch_bounds__(256) void gemm_kernel(
    const float* __restrict__ out_w, const float* __restrict__ bias,
    float* __restrict__ out)
{
    __shared__ u64 hs[128 * 16];   // (h,h) packed, 16 KB

    int rb = blockIdx.y * 128;
    int vb = blockIdx.x * 1024;

    for (int idx = threadIdx.x; idx < 128 * 16; idx += 256) {
        float v = g_H[(size_t)rb * 16 + idx];
        hs[idx] = pack2(v, v);
    }
    __syncthreads();

    int v0 = vb + threadIdx.x * 4;
    if (v0 >= VOCAB) return;

    float wv[4][16];
    #pragma unroll
    for (int r = 0; r < 4; r++) {
        const float4* wr = (const float4*)(out_w + (size_t)(v0 + r) * 16);
        #pragma unroll
        for (int c = 0; c < 4; c++)
            ((float4*)wv[r])[c] = __ldg(wr + c);
    }
    u64 w2a[16], w2b[16];
    #pragma unroll
    for (int k = 0; k < 16; k++) {
        w2a[k] = pack2(wv[0][k], wv[1][k]);
        w2b[k] = pack2(wv[2][k], wv[3][k]);
    }
    u64 ba = *(const u64*)(bias + v0);
    u64 bb = *(const u64*)(bias + v0 + 2);

    for (int r = 0; r < 128; r++) {
        const ulonglong2* hp = (const ulonglong2*)(hs + r * 16);
        u64 aA = ba, aB = bb;
        #pragma unroll
        for (int k = 0; k < 16; k += 2) {
            ulonglong2 hh = hp[k >> 1];
            aA = ffma2(hh.x, w2a[k],     aA);
            aB = ffma2(hh.x, w2b[k],     aB);
            aA = ffma2(hh.y, w2a[k + 1], aA);
            aB = ffma2(hh.y, w2b[k + 1], aB);
        }
        float2 fa = unpack2(aA);
        float2 fb = unpack2(aB);
        __stcs((float4*)(out + (size_t)(rb + r) * VOCAB + v0),
               make_float4(fa.x, fa.y, fb.x, fb.y));
    }
}

// ---------------- launch ----------------
extern "C" void kernel_launch(void* const* d_in, const int* in_sizes, int n_in,
                              void* d_out, int out_size)
{
    const int*   seq   = (const int*)d_in[0];
    const float* embed = (const float*)d_in[1];
    const float* Wh    = (const float*)d_in[2];
    const float* Wx_w  = (const float*)d_in[3];
    const float* Wx_b  = (const float*)d_in[4];
    const float* out_w = (const float*)d_in[5];
    const float* out_b = (const float*)d_in[6];
    float* out = (float*)d_out;

    prep_kernel<<<VOCAB / 64, 256>>>(embed, Wx_w, Wx_b);          // 500 blocks

    rnn_kernel<<<B_DIM / 16, 256>>>(seq, Wh);                     // 256 blocks

    dim3 ggrid((VOCAB + 1023) / 1024, B_DIM / 128);               // (32, 32)
    gemm_kernel<<<ggrid, 256>>>(out_w, out_b, out);
}